// round 10
// baseline (speedup 1.0000x reference)
#include <cuda_runtime.h>
#include <cstdint>

#define HD   1024
#define LSEQ 512
#define LAB  122
#define G4   (4*HD)     // 4096
#define IN5  (5*HD)     // 5120
#define NCTA 128
#define SENT 0x7FC00000u   // qNaN sentinel
#define AROW 20            // 16 k-floats + 4 pad (conflict-free, 16B-aligned rows)

typedef unsigned long long ull;

// ---------------- scratch (static __device__, no allocs) ----------------
__device__ float g_G[(size_t)LSEQ * G4];     // precomputed input gates + bias (8 MB)
__device__ float g_outs[(size_t)LSEQ * HD];  // h_t for all t; doubles as sync medium (2 MB)

// ---------------- ncu steering pad (no-op); recur must be launch index 3 ----
__global__ void pad_kernel() {}

// ---------------- reset: poison g_outs with sentinel ----------------
__global__ void reset_kernel() {
    size_t i = (size_t)blockIdx.x * blockDim.x + threadIdx.x;
    uint32_t* p = (uint32_t*)g_outs;
    p[2 * i]     = SENT;
    p[2 * i + 1] = SENT;
}

// ---------------- mma helper ----------------
__device__ __forceinline__ void mma_tf32(float* d, const uint32_t* a, const uint32_t* b) {
    asm volatile(
        "mma.sync.aligned.m16n8k8.row.col.f32.tf32.tf32.f32 "
        "{%0,%1,%2,%3}, {%4,%5,%6,%7}, {%8,%9}, {%0,%1,%2,%3};\n"
        : "+f"(d[0]), "+f"(d[1]), "+f"(d[2]), "+f"(d[3])
        : "r"(a[0]), "r"(a[1]), "r"(a[2]), "r"(a[3]), "r"(b[0]), "r"(b[1]));
}

// ---------------- packed f32x2 helpers ----------------
__device__ __forceinline__ ull packf2(float lo, float hi) {
    ull p;
    asm("mov.b64 %0, {%1, %2};" : "=l"(p) : "f"(lo), "f"(hi));
    return p;
}
__device__ __forceinline__ void fma2(ull& acc, ull w, ull h) {
    asm("fma.rn.f32x2 %0, %1, %2, %0;" : "+l"(acc) : "l"(w), "l"(h));
}
__device__ __forceinline__ float sum2(ull a) {
    float lo, hi;
    asm("mov.b64 {%0, %1}, %2;" : "=f"(lo), "=f"(hi) : "l"(a));
    return lo + hi;
}

// ---------------- Phase 1: G = F @ W_x^T + (b_ih + b_hh) ----------------
// 128x128 tile, BK=16, 256 threads (8 warps: 2m x 4n of 64x32).
// cp.async 2-stage pipeline; raw fp32 bits -> tf32 mma (HW trunc).
// launch_bounds(256,2): cap 112 regs -> 2 CTAs/SM so one CTA's mma burst
// hides the other's cp.async wait (fixes occ=12.5%/tensor=32% from R9 profile).
__global__ void __launch_bounds__(256, 2) gemm_kernel(
    const float* __restrict__ x, const float* __restrict__ hi,
    const float* __restrict__ W_ih,
    const float* __restrict__ b_ih, const float* __restrict__ b_hh)
{
    __shared__ __align__(16) float sA[2][128][AROW];   // 20480 B
    __shared__ __align__(16) float sB[2][128][AROW];   // 20480 B

    const int tid  = threadIdx.x;
    const int warp = tid >> 5, lane = tid & 31;
    const int grp  = lane >> 2, q = lane & 3;
    const int wm   = warp & 1;         // 0..1 -> 64-row m half
    const int wn   = warp >> 1;        // 0..3 -> 32-col n quarter
    const int tm0  = blockIdx.y * 128;
    const int rn0  = blockIdx.x * 128;

    const int ldRow = tid >> 2;        // 0..63 (+64 for second chunk)
    const int ldCh  = tid & 3;         // 16B chunk within the 16-float k slab

    uint32_t aBase = (uint32_t)__cvta_generic_to_shared(&sA[0][0][0]);
    uint32_t bBase = (uint32_t)__cvta_generic_to_shared(&sB[0][0][0]);

    auto issue_stage = [&](int kt) {
        int stage = kt & 1;
        int kg = kt * 16 + ldCh * 4;
        #pragma unroll
        for (int i = 0; i < 2; i++) {
            int row = ldRow + i * 64;
            const float* gA = (kg < 2048)
                ? (x  + (size_t)(tm0 + row) * 2048 + kg)
                : (hi + (size_t)(tm0 + row) * 2048 + kg - 2048);
            uint32_t dA = aBase + (((stage * 128 + row) * AROW) + ldCh * 4) * 4;
            asm volatile("cp.async.cg.shared.global [%0], [%1], 16;" :: "r"(dA), "l"(gA));
            const float* gB = W_ih + (size_t)(rn0 + row) * IN5 + kg;
            uint32_t dB = bBase + (((stage * 128 + row) * AROW) + ldCh * 4) * 4;
            asm volatile("cp.async.cg.shared.global [%0], [%1], 16;" :: "r"(dB), "l"(gB));
        }
        asm volatile("cp.async.commit_group;");
    };

    float acc[4][4][4];
    #pragma unroll
    for (int a = 0; a < 4; a++)
        #pragma unroll
        for (int b = 0; b < 4; b++)
            #pragma unroll
            for (int c = 0; c < 4; c++) acc[a][b][c] = 0.f;

    issue_stage(0);

    for (int kt = 0; kt < 256; kt++) {
        if (kt < 255) {
            issue_stage(kt + 1);
            asm volatile("cp.async.wait_group 1;");
        } else {
            asm volatile("cp.async.wait_group 0;");
        }
        __syncthreads();

        const float* A = &sA[kt & 1][0][0];
        const float* B = &sB[kt & 1][0][0];

        #pragma unroll
        for (int kk = 0; kk < 16; kk += 8) {
            uint32_t af[4][4], bf[4][2];
            #pragma unroll
            for (int mi = 0; mi < 4; mi++) {
                int rb = wm * 64 + mi * 16;
                af[mi][0] = __float_as_uint(A[(rb + grp    ) * AROW + kk + q    ]);
                af[mi][1] = __float_as_uint(A[(rb + grp + 8) * AROW + kk + q    ]);
                af[mi][2] = __float_as_uint(A[(rb + grp    ) * AROW + kk + q + 4]);
                af[mi][3] = __float_as_uint(A[(rb + grp + 8) * AROW + kk + q + 4]);
            }
            #pragma unroll
            for (int ni = 0; ni < 4; ni++) {
                int nb = wn * 32 + ni * 8;
                bf[ni][0] = __float_as_uint(B[(nb + grp) * AROW + kk + q    ]);
                bf[ni][1] = __float_as_uint(B[(nb + grp) * AROW + kk + q + 4]);
            }
            #pragma unroll
            for (int mi = 0; mi < 4; mi++)
                #pragma unroll
                for (int ni = 0; ni < 4; ni++)
                    mma_tf32(acc[mi][ni], af[mi], bf[ni]);
        }
        __syncthreads();
    }

    #pragma unroll
    for (int mi = 0; mi < 4; mi++)
        #pragma unroll
        for (int ni = 0; ni < 4; ni++) {
            int r0 = tm0 + wm * 64 + mi * 16 + grp;
            int c0 = rn0 + wn * 32 + ni * 8 + 2 * q;
            float bia0 = b_ih[c0]     + b_hh[c0];
            float bia1 = b_ih[c0 + 1] + b_hh[c0 + 1];
            g_G[(size_t)r0 * G4 + c0]           = acc[mi][ni][0] + bia0;
            g_G[(size_t)r0 * G4 + c0 + 1]       = acc[mi][ni][1] + bia1;
            g_G[(size_t)(r0 + 8) * G4 + c0]     = acc[mi][ni][2] + bia0;
            g_G[(size_t)(r0 + 8) * G4 + c0 + 1] = acc[mi][ni][3] + bia1;
        }
}

// ---------------- Phase 2: persistent recurrence ----------------
// 128 CTAs x 544 threads: warps 0-15 = dot warps (register-resident W_r),
// warp 16 = epilogue warp. Sentinel data-carried handoff,
// 2-in-flight rotating poll, bar.arrive/bar.sync split. (R9-proven; frozen.)
__global__ void __launch_bounds__(544, 1) recur_kernel(
    const float* __restrict__ W_ih, const float* __restrict__ W_hh)
{
    __shared__ float sh_h[HD];            // warp-private 64-float slices
    __shared__ float sh_part[2][16][32];  // parity double buffer

    const int tid  = threadIdx.x;
    const int w    = tid >> 5, l = tid & 31;
    const int gate = l >> 3, jl = l & 7;
    const int j    = blockIdx.x * 8 + jl;
    const int rg   = gate * HD + j;
    const bool dot_warp = (w < 16);
    const int kb   = (w & 15) * 64;

    // dot warps: fuse recurrent weights, packed f32x2 (fp32-exact)
    ull pw[32];
    if (dot_warp) {
        #pragma unroll
        for (int i = 0; i < 16; i++) {
            float4 a = *(const float4*)(W_ih + (size_t)rg * IN5 + G4 + kb + 4 * i);
            float4 b = *(const float4*)(W_hh + (size_t)rg * HD + kb + 4 * i);
            pw[2*i]   = packf2(a.x + b.x, a.y + b.y);
            pw[2*i+1] = packf2(a.z + b.z, a.w + b.w);
        }
    }

    float c = 0.f;          // cell state (epilogue warp, lanes 0-7)

    for (int t = 0; t < LSEQ; t++) {
        if (dot_warp) {
            float partial = 0.f;
            if (t > 0) {
                // rotating 2-in-flight poll: lane owns 8B of the 64-float slice
                const float* p = g_outs + (size_t)(t - 1) * HD + kb + 2 * l;
                float2 a, b, hv;
                bool got = false;
                asm volatile("ld.global.cg.v2.f32 {%0,%1}, [%2];"
                             : "=f"(a.x), "=f"(a.y) : "l"(p));
                asm volatile("ld.global.cg.v2.f32 {%0,%1}, [%2];"
                             : "=f"(b.x), "=f"(b.y) : "l"(p));
                for (;;) {
                    if (!got && __float_as_uint(a.y) != SENT
                             && __float_as_uint(a.x) != SENT) { hv = a; got = true; }
                    if (__all_sync(0xffffffffu, got)) break;
                    asm volatile("ld.global.cg.v2.f32 {%0,%1}, [%2];"
                                 : "=f"(a.x), "=f"(a.y) : "l"(p));
                    if (!got && __float_as_uint(b.y) != SENT
                             && __float_as_uint(b.x) != SENT) { hv = b; got = true; }
                    if (__all_sync(0xffffffffu, got)) break;
                    asm volatile("ld.global.cg.v2.f32 {%0,%1}, [%2];"
                                 : "=f"(b.x), "=f"(b.y) : "l"(p));
                }
                ((float2*)(sh_h + kb))[l] = hv;
                __syncwarp();

                // dot: 32 FFMA2 against packed register weights
                ull a0 = packf2(0.f, 0.f), a1 = packf2(0.f, 0.f);
                const ulonglong2* h8 = (const ulonglong2*)(sh_h + kb);
                #pragma unroll
                for (int i = 0; i < 16; i++) {
                    ulonglong2 hvv = h8[i];
                    fma2(a0, pw[2*i],     hvv.x);
                    fma2(a1, pw[2*i + 1], hvv.y);
                }
                partial = sum2(a0) + sum2(a1);
            }
            sh_part[t & 1][w][l] = partial;
            // arrive-only: roll straight into next step's poll
            asm volatile("bar.arrive 1, 544;");
        } else {
            // epilogue warp: prefetch gate pre-activations while dots run
            float gpre = __ldcg(&g_G[(size_t)t * G4 + rg]);
            asm volatile("bar.sync 1, 544;");   // waits for all 512 dot threads

            // reduce 16 partials (tree)
            float p0 = sh_part[t & 1][0][l],  p1 = sh_part[t & 1][1][l];
            float p2 = sh_part[t & 1][2][l],  p3 = sh_part[t & 1][3][l];
            float p4 = sh_part[t & 1][4][l],  p5 = sh_part[t & 1][5][l];
            float p6 = sh_part[t & 1][6][l],  p7 = sh_part[t & 1][7][l];
            float p8 = sh_part[t & 1][8][l],  p9 = sh_part[t & 1][9][l];
            float pA = sh_part[t & 1][10][l], pB = sh_part[t & 1][11][l];
            float pC = sh_part[t & 1][12][l], pD = sh_part[t & 1][13][l];
            float pE = sh_part[t & 1][14][l], pF = sh_part[t & 1][15][l];
            float s = gpre + (((p0+p1)+(p2+p3)) + ((p4+p5)+(p6+p7)))
                           + (((p8+p9)+(pA+pB)) + ((pC+pD)+(pE+pF)));

            // parallel per-gate nonlinearity BEFORE gather (1 expf, all lanes)
            float arg = (gate == 2) ? (2.f * s) : s;
            float e   = __expf(-arg);
            float sig = __fdividef(1.f, 1.f + e);
            float v   = (gate == 2) ? (2.f * sig - 1.f) : sig;   // tanh for 'g'

            float ig = __shfl_sync(0xffffffffu, v, jl);
            float fg = __shfl_sync(0xffffffffu, v, jl + 8);
            float tg = __shfl_sync(0xffffffffu, v, jl + 16);
            float og = __shfl_sync(0xffffffffu, v, jl + 24);
            if (l < 8) {
                c = fg * c + ig * tg;
                float tc = 2.f * __fdividef(1.f, 1.f + __expf(-2.f * c)) - 1.f;
                float hn = og * tc;
                // single coalesced sector store = data + readiness in one shot
                __stcg(&g_outs[(size_t)t * HD + j], hn);
            }
        }
    }
}

// ---------------- Phase 3: out = outs @ W_fc^T + b_fc (tiled) ----------------
#define FC_TT 4
__global__ void __launch_bounds__(128) fc_kernel(
    const float* __restrict__ W_fc, const float* __restrict__ b_fc,
    float* __restrict__ out)
{
    __shared__ float sw[LAB][65];
    __shared__ float so[FC_TT][64];

    const int tid = threadIdx.x;
    const int t0  = blockIdx.x * FC_TT;

    float acc[FC_TT];
    #pragma unroll
    for (int tt = 0; tt < FC_TT; tt++) acc[tt] = 0.f;

    for (int kc = 0; kc < HD; kc += 64) {
        for (int idx = tid; idx < LAB * 64; idx += 128) {
            int r = idx >> 6, cc = idx & 63;
            sw[r][cc] = W_fc[(size_t)r * HD + kc + cc];
        }
        for (int idx = tid; idx < FC_TT * 64; idx += 128) {
            int tt = idx >> 6, cc = idx & 63;
            so[tt][cc] = g_outs[(size_t)(t0 + tt) * HD + kc + cc];
        }
        __syncthreads();

        if (tid < LAB) {
            #pragma unroll
            for (int k = 0; k < 64; k += 4) {
                float w0 = sw[tid][k], w1 = sw[tid][k+1];
                float w2 = sw[tid][k+2], w3 = sw[tid][k+3];
                #pragma unroll
                for (int tt = 0; tt < FC_TT; tt++) {
                    float4 ov = *(const float4*)&so[tt][k];
                    acc[tt] += w0*ov.x + w1*ov.y + w2*ov.z + w3*ov.w;
                }
            }
        }
        __syncthreads();
    }

    if (tid < LAB) {
        float bb = b_fc[tid];
        #pragma unroll
        for (int tt = 0; tt < FC_TT; tt++)
            out[(size_t)(t0 + tt) * LAB + tid] = acc[tt] + bb;
    }
}

// ---------------- launch ----------------
extern "C" void kernel_launch(void* const* d_in, const int* in_sizes, int n_in,
                              void* d_out, int out_size)
{
    const float* x    = (const float*)d_in[0];
    const float* hi   = (const float*)d_in[1];
    const float* W_ih = (const float*)d_in[2];
    const float* W_hh = (const float*)d_in[3];
    const float* b_ih = (const float*)d_in[4];
    const float* b_hh = (const float*)d_in[5];
    const float* W_fc = (const float*)d_in[6];
    const float* b_fc = (const float*)d_in[7];
    float* out = (float*)d_out;

    pad_kernel<<<1, 32>>>();                            // idx 0
    reset_kernel<<<512, 512>>>();                       // idx 1: poison g_outs
    gemm_kernel<<<dim3(G4 / 128, LSEQ / 128), 256>>>(x, hi, W_ih, b_ih, b_hh); // idx 2
    recur_kernel<<<NCTA, 544>>>(W_ih, W_hh);            // idx 3 -> ncu
    fc_kernel<<<LSEQ / FC_TT, 128>>>(W_fc, b_fc, out);  // idx 4
}

// round 12
// speedup vs baseline: 1.0029x; 1.0029x over previous
#include <cuda_runtime.h>
#include <cstdint>

#define HD   1024
#define LSEQ 512
#define LAB  122
#define G4   (4*HD)     // 4096
#define IN5  (5*HD)     // 5120
#define NCTA 128
#define SENT 0x7FC00000u   // qNaN sentinel
#define AROW 20            // 16 k-floats + 4 pad (conflict-free, 16B-aligned rows)
#define GSTAGES 4
#define GEMM_SMEM (GSTAGES * 128 * AROW * 4 * 2)   // 81920 B

typedef unsigned long long ull;

// ---------------- scratch (static __device__, no allocs) ----------------
__device__ float g_G[(size_t)LSEQ * G4];     // precomputed input gates + bias (8 MB)
__device__ float g_outs[(size_t)LSEQ * HD];  // h_t for all t; doubles as sync medium (2 MB)

// ---------------- ncu steering pad (no-op); recur must be launch index 3 ----
__global__ void pad_kernel() {}

// ---------------- reset: poison g_outs with sentinel ----------------
__global__ void reset_kernel() {
    size_t i = (size_t)blockIdx.x * blockDim.x + threadIdx.x;
    uint32_t* p = (uint32_t*)g_outs;
    p[2 * i]     = SENT;
    p[2 * i + 1] = SENT;
}

// ---------------- mma helper ----------------
__device__ __forceinline__ void mma_tf32(float* d, const uint32_t* a, const uint32_t* b) {
    asm volatile(
        "mma.sync.aligned.m16n8k8.row.col.f32.tf32.tf32.f32 "
        "{%0,%1,%2,%3}, {%4,%5,%6,%7}, {%8,%9}, {%0,%1,%2,%3};\n"
        : "+f"(d[0]), "+f"(d[1]), "+f"(d[2]), "+f"(d[3])
        : "r"(a[0]), "r"(a[1]), "r"(a[2]), "r"(a[3]), "r"(b[0]), "r"(b[1]));
}

// ---------------- packed f32x2 helpers ----------------
__device__ __forceinline__ ull packf2(float lo, float hi) {
    ull p;
    asm("mov.b64 %0, {%1, %2};" : "=l"(p) : "f"(lo), "f"(hi));
    return p;
}
__device__ __forceinline__ void fma2(ull& acc, ull w, ull h) {
    asm("fma.rn.f32x2 %0, %1, %2, %0;" : "+l"(acc) : "l"(w), "l"(h));
}
__device__ __forceinline__ float sum2(ull a) {
    float lo, hi;
    asm("mov.b64 {%0, %1}, %2;" : "=f"(lo), "=f"(hi) : "l"(a));
    return lo + hi;
}

// ---------------- Phase 1: G = F @ W_x^T + (b_ih + b_hh) ----------------
// 128x128 tile, BK=16, 256 threads (8 warps: 2m x 4n of 64x32).
// 4-stage cp.async pipeline (80KB dyn smem, opt-in). Issue-early into stage
// (kt+3)&3 (distinct from consumed kt&3), tail: wait_group min(3, 255-kt).
__global__ void __launch_bounds__(256) gemm_kernel(
    const float* __restrict__ x, const float* __restrict__ hi,
    const float* __restrict__ W_ih,
    const float* __restrict__ b_ih, const float* __restrict__ b_hh)
{
    extern __shared__ __align__(16) float smem[];
    float* sA = smem;                           // [GSTAGES][128][AROW]
    float* sB = smem + GSTAGES * 128 * AROW;    // [GSTAGES][128][AROW]

    const int tid  = threadIdx.x;
    const int warp = tid >> 5, lane = tid & 31;
    const int grp  = lane >> 2, q = lane & 3;
    const int wm   = warp & 1;         // 0..1 -> 64-row m half
    const int wn   = warp >> 1;        // 0..3 -> 32-col n quarter
    const int tm0  = blockIdx.y * 128;
    const int rn0  = blockIdx.x * 128;

    const int ldRow = tid >> 2;        // 0..63 (+64 for second chunk)
    const int ldCh  = tid & 3;         // 16B chunk within the 16-float k slab

    uint32_t aBase = (uint32_t)__cvta_generic_to_shared(sA);
    uint32_t bBase = (uint32_t)__cvta_generic_to_shared(sB);

    auto issue_stage = [&](int kt) {
        int stage = kt & (GSTAGES - 1);
        int kg = kt * 16 + ldCh * 4;
        #pragma unroll
        for (int i = 0; i < 2; i++) {
            int row = ldRow + i * 64;
            const float* gA = (kg < 2048)
                ? (x  + (size_t)(tm0 + row) * 2048 + kg)
                : (hi + (size_t)(tm0 + row) * 2048 + kg - 2048);
            uint32_t dA = aBase + (((stage * 128 + row) * AROW) + ldCh * 4) * 4;
            asm volatile("cp.async.cg.shared.global [%0], [%1], 16;" :: "r"(dA), "l"(gA));
            const float* gB = W_ih + (size_t)(rn0 + row) * IN5 + kg;
            uint32_t dB = bBase + (((stage * 128 + row) * AROW) + ldCh * 4) * 4;
            asm volatile("cp.async.cg.shared.global [%0], [%1], 16;" :: "r"(dB), "l"(gB));
        }
        asm volatile("cp.async.commit_group;");
    };

    float acc[4][4][4];
    #pragma unroll
    for (int a = 0; a < 4; a++)
        #pragma unroll
        for (int b = 0; b < 4; b++)
            #pragma unroll
            for (int c = 0; c < 4; c++) acc[a][b][c] = 0.f;

    issue_stage(0);
    issue_stage(1);
    issue_stage(2);

    for (int kt = 0; kt < 256; kt++) {
        // issue-early: stage (kt+3)&3 is not the one consumed this iter
        if (kt <= 252) {
            issue_stage(kt + 3);
            asm volatile("cp.async.wait_group 3;");   // group kt complete
        } else if (kt == 253) {
            asm volatile("cp.async.wait_group 2;");
        } else if (kt == 254) {
            asm volatile("cp.async.wait_group 1;");
        } else {
            asm volatile("cp.async.wait_group 0;");
        }
        __syncthreads();

        const float* A = sA + (kt & (GSTAGES - 1)) * 128 * AROW;
        const float* B = sB + (kt & (GSTAGES - 1)) * 128 * AROW;

        #pragma unroll
        for (int kk = 0; kk < 16; kk += 8) {
            uint32_t af[4][4], bf[4][2];
            #pragma unroll
            for (int mi = 0; mi < 4; mi++) {
                int rb = wm * 64 + mi * 16;
                af[mi][0] = __float_as_uint(A[(rb + grp    ) * AROW + kk + q    ]);
                af[mi][1] = __float_as_uint(A[(rb + grp + 8) * AROW + kk + q    ]);
                af[mi][2] = __float_as_uint(A[(rb + grp    ) * AROW + kk + q + 4]);
                af[mi][3] = __float_as_uint(A[(rb + grp + 8) * AROW + kk + q + 4]);
            }
            #pragma unroll
            for (int ni = 0; ni < 4; ni++) {
                int nb = wn * 32 + ni * 8;
                bf[ni][0] = __float_as_uint(B[(nb + grp) * AROW + kk + q    ]);
                bf[ni][1] = __float_as_uint(B[(nb + grp) * AROW + kk + q + 4]);
            }
            #pragma unroll
            for (int mi = 0; mi < 4; mi++)
                #pragma unroll
                for (int ni = 0; ni < 4; ni++)
                    mma_tf32(acc[mi][ni], af[mi], bf[ni]);
        }
        __syncthreads();   // readers done before stage (kt+4) refill next iters
    }

    #pragma unroll
    for (int mi = 0; mi < 4; mi++)
        #pragma unroll
        for (int ni = 0; ni < 4; ni++) {
            int r0 = tm0 + wm * 64 + mi * 16 + grp;
            int c0 = rn0 + wn * 32 + ni * 8 + 2 * q;
            float bia0 = b_ih[c0]     + b_hh[c0];
            float bia1 = b_ih[c0 + 1] + b_hh[c0 + 1];
            g_G[(size_t)r0 * G4 + c0]           = acc[mi][ni][0] + bia0;
            g_G[(size_t)r0 * G4 + c0 + 1]       = acc[mi][ni][1] + bia1;
            g_G[(size_t)(r0 + 8) * G4 + c0]     = acc[mi][ni][2] + bia0;
            g_G[(size_t)(r0 + 8) * G4 + c0 + 1] = acc[mi][ni][3] + bia1;
        }
}

// ---------------- Phase 2: persistent recurrence (FROZEN from R9/R10) ----------------
// 128 CTAs x 544 threads: warps 0-15 = dot warps (register-resident W_r),
// warp 16 = epilogue warp. Sentinel handoff, rotating 2-in-flight poll,
// bar.arrive/bar.sync split.
__global__ void __launch_bounds__(544, 1) recur_kernel(
    const float* __restrict__ W_ih, const float* __restrict__ W_hh)
{
    __shared__ float sh_h[HD];            // warp-private 64-float slices
    __shared__ float sh_part[2][16][32];  // parity double buffer

    const int tid  = threadIdx.x;
    const int w    = tid >> 5, l = tid & 31;
    const int gate = l >> 3, jl = l & 7;
    const int j    = blockIdx.x * 8 + jl;
    const int rg   = gate * HD + j;
    const bool dot_warp = (w < 16);
    const int kb   = (w & 15) * 64;

    // dot warps: fuse recurrent weights, packed f32x2 (fp32-exact)
    ull pw[32];
    if (dot_warp) {
        #pragma unroll
        for (int i = 0; i < 16; i++) {
            float4 a = *(const float4*)(W_ih + (size_t)rg * IN5 + G4 + kb + 4 * i);
            float4 b = *(const float4*)(W_hh + (size_t)rg * HD + kb + 4 * i);
            pw[2*i]   = packf2(a.x + b.x, a.y + b.y);
            pw[2*i+1] = packf2(a.z + b.z, a.w + b.w);
        }
    }

    float c = 0.f;          // cell state (epilogue warp, lanes 0-7)

    for (int t = 0; t < LSEQ; t++) {
        if (dot_warp) {
            float partial = 0.f;
            if (t > 0) {
                // rotating 2-in-flight poll: lane owns 8B of the 64-float slice
                const float* p = g_outs + (size_t)(t - 1) * HD + kb + 2 * l;
                float2 a, b, hv;
                bool got = false;
                asm volatile("ld.global.cg.v2.f32 {%0,%1}, [%2];"
                             : "=f"(a.x), "=f"(a.y) : "l"(p));
                asm volatile("ld.global.cg.v2.f32 {%0,%1}, [%2];"
                             : "=f"(b.x), "=f"(b.y) : "l"(p));
                for (;;) {
                    if (!got && __float_as_uint(a.y) != SENT
                             && __float_as_uint(a.x) != SENT) { hv = a; got = true; }
                    if (__all_sync(0xffffffffu, got)) break;
                    asm volatile("ld.global.cg.v2.f32 {%0,%1}, [%2];"
                                 : "=f"(a.x), "=f"(a.y) : "l"(p));
                    if (!got && __float_as_uint(b.y) != SENT
                             && __float_as_uint(b.x) != SENT) { hv = b; got = true; }
                    if (__all_sync(0xffffffffu, got)) break;
                    asm volatile("ld.global.cg.v2.f32 {%0,%1}, [%2];"
                                 : "=f"(b.x), "=f"(b.y) : "l"(p));
                }
                ((float2*)(sh_h + kb))[l] = hv;
                __syncwarp();

                // dot: 32 FFMA2 against packed register weights
                ull a0 = packf2(0.f, 0.f), a1 = packf2(0.f, 0.f);
                const ulonglong2* h8 = (const ulonglong2*)(sh_h + kb);
                #pragma unroll
                for (int i = 0; i < 16; i++) {
                    ulonglong2 hvv = h8[i];
                    fma2(a0, pw[2*i],     hvv.x);
                    fma2(a1, pw[2*i + 1], hvv.y);
                }
                partial = sum2(a0) + sum2(a1);
            }
            sh_part[t & 1][w][l] = partial;
            // arrive-only: roll straight into next step's poll
            asm volatile("bar.arrive 1, 544;");
        } else {
            // epilogue warp: prefetch gate pre-activations while dots run
            float gpre = __ldcg(&g_G[(size_t)t * G4 + rg]);
            asm volatile("bar.sync 1, 544;");   // waits for all 512 dot threads

            // reduce 16 partials (tree)
            float p0 = sh_part[t & 1][0][l],  p1 = sh_part[t & 1][1][l];
            float p2 = sh_part[t & 1][2][l],  p3 = sh_part[t & 1][3][l];
            float p4 = sh_part[t & 1][4][l],  p5 = sh_part[t & 1][5][l];
            float p6 = sh_part[t & 1][6][l],  p7 = sh_part[t & 1][7][l];
            float p8 = sh_part[t & 1][8][l],  p9 = sh_part[t & 1][9][l];
            float pA = sh_part[t & 1][10][l], pB = sh_part[t & 1][11][l];
            float pC = sh_part[t & 1][12][l], pD = sh_part[t & 1][13][l];
            float pE = sh_part[t & 1][14][l], pF = sh_part[t & 1][15][l];
            float s = gpre + (((p0+p1)+(p2+p3)) + ((p4+p5)+(p6+p7)))
                           + (((p8+p9)+(pA+pB)) + ((pC+pD)+(pE+pF)));

            // parallel per-gate nonlinearity BEFORE gather (1 expf, all lanes)
            float arg = (gate == 2) ? (2.f * s) : s;
            float e   = __expf(-arg);
            float sig = __fdividef(1.f, 1.f + e);
            float v   = (gate == 2) ? (2.f * sig - 1.f) : sig;   // tanh for 'g'

            float ig = __shfl_sync(0xffffffffu, v, jl);
            float fg = __shfl_sync(0xffffffffu, v, jl + 8);
            float tg = __shfl_sync(0xffffffffu, v, jl + 16);
            float og = __shfl_sync(0xffffffffu, v, jl + 24);
            if (l < 8) {
                c = fg * c + ig * tg;
                float tc = 2.f * __fdividef(1.f, 1.f + __expf(-2.f * c)) - 1.f;
                float hn = og * tc;
                // single coalesced sector store = data + readiness in one shot
                __stcg(&g_outs[(size_t)t * HD + j], hn);
            }
        }
    }
}

// ---------------- Phase 3: out = outs @ W_fc^T + b_fc (tiled) ----------------
#define FC_TT 4
__global__ void __launch_bounds__(128) fc_kernel(
    const float* __restrict__ W_fc, const float* __restrict__ b_fc,
    float* __restrict__ out)
{
    __shared__ float sw[LAB][65];
    __shared__ float so[FC_TT][64];

    const int tid = threadIdx.x;
    const int t0  = blockIdx.x * FC_TT;

    float acc[FC_TT];
    #pragma unroll
    for (int tt = 0; tt < FC_TT; tt++) acc[tt] = 0.f;

    for (int kc = 0; kc < HD; kc += 64) {
        for (int idx = tid; idx < LAB * 64; idx += 128) {
            int r = idx >> 6, cc = idx & 63;
            sw[r][cc] = W_fc[(size_t)r * HD + kc + cc];
        }
        for (int idx = tid; idx < FC_TT * 64; idx += 128) {
            int tt = idx >> 6, cc = idx & 63;
            so[tt][cc] = g_outs[(size_t)(t0 + tt) * HD + kc + cc];
        }
        __syncthreads();

        if (tid < LAB) {
            #pragma unroll
            for (int k = 0; k < 64; k += 4) {
                float w0 = sw[tid][k], w1 = sw[tid][k+1];
                float w2 = sw[tid][k+2], w3 = sw[tid][k+3];
                #pragma unroll
                for (int tt = 0; tt < FC_TT; tt++) {
                    float4 ov = *(const float4*)&so[tt][k];
                    acc[tt] += w0*ov.x + w1*ov.y + w2*ov.z + w3*ov.w;
                }
            }
        }
        __syncthreads();
    }

    if (tid < LAB) {
        float bb = b_fc[tid];
        #pragma unroll
        for (int tt = 0; tt < FC_TT; tt++)
            out[(size_t)(t0 + tt) * LAB + tid] = acc[tt] + bb;
    }
}

// ---------------- launch ----------------
extern "C" void kernel_launch(void* const* d_in, const int* in_sizes, int n_in,
                              void* d_out, int out_size)
{
    const float* x    = (const float*)d_in[0];
    const float* hi   = (const float*)d_in[1];
    const float* W_ih = (const float*)d_in[2];
    const float* W_hh = (const float*)d_in[3];
    const float* b_ih = (const float*)d_in[4];
    const float* b_hh = (const float*)d_in[5];
    const float* W_fc = (const float*)d_in[6];
    const float* b_fc = (const float*)d_in[7];
    float* out = (float*)d_out;

    static bool attr_done = false;
    if (!attr_done) {
        cudaFuncSetAttribute(gemm_kernel,
                             cudaFuncAttributeMaxDynamicSharedMemorySize, GEMM_SMEM);
        attr_done = true;
    }

    pad_kernel<<<1, 32>>>();                            // idx 0
    reset_kernel<<<512, 512>>>();                       // idx 1: poison g_outs
    gemm_kernel<<<dim3(G4 / 128, LSEQ / 128), 256, GEMM_SMEM>>>(x, hi, W_ih, b_ih, b_hh); // idx 2
    recur_kernel<<<NCTA, 544>>>(W_ih, W_hh);            // idx 3 -> ncu
    fc_kernel<<<LSEQ / FC_TT, 128>>>(W_fc, b_fc, out);  // idx 4
}

// round 13
// speedup vs baseline: 1.0176x; 1.0147x over previous
#include <cuda_runtime.h>
#include <cstdint>

#define HD   1024
#define LSEQ 512
#define LAB  122
#define G4   (4*HD)     // 4096
#define IN5  (5*HD)     // 5120
#define NCTA 128
#define SENT 0x7FC00000u   // qNaN sentinel
#define AROW 36            // 32 k-floats + 4 pad (conflict-free: 36 mod 32 = 4)
#define GEMM_SMEM (2 * 128 * AROW * 4 * 2)   // 73728 B (2 stages, A + B)

typedef unsigned long long ull;

// ---------------- scratch (static __device__, no allocs) ----------------
__device__ float g_G[(size_t)LSEQ * G4];     // precomputed input gates + bias (8 MB)
__device__ float g_outs[(size_t)LSEQ * HD];  // h_t for all t; doubles as sync medium (2 MB)

// ---------------- ncu steering pads (no-op); gemm must be launch index 3 ----
__global__ void pad_kernel() {}

// ---------------- reset: poison g_outs with sentinel ----------------
__global__ void reset_kernel() {
    size_t i = (size_t)blockIdx.x * blockDim.x + threadIdx.x;
    uint32_t* p = (uint32_t*)g_outs;
    p[2 * i]     = SENT;
    p[2 * i + 1] = SENT;
}

// ---------------- mma helper ----------------
__device__ __forceinline__ void mma_tf32(float* d, const uint32_t* a, const uint32_t* b) {
    asm volatile(
        "mma.sync.aligned.m16n8k8.row.col.f32.tf32.tf32.f32 "
        "{%0,%1,%2,%3}, {%4,%5,%6,%7}, {%8,%9}, {%0,%1,%2,%3};\n"
        : "+f"(d[0]), "+f"(d[1]), "+f"(d[2]), "+f"(d[3])
        : "r"(a[0]), "r"(a[1]), "r"(a[2]), "r"(a[3]), "r"(b[0]), "r"(b[1]));
}

// ---------------- packed f32x2 helpers ----------------
__device__ __forceinline__ ull packf2(float lo, float hi) {
    ull p;
    asm("mov.b64 %0, {%1, %2};" : "=l"(p) : "f"(lo), "f"(hi));
    return p;
}
__device__ __forceinline__ void fma2(ull& acc, ull w, ull h) {
    asm("fma.rn.f32x2 %0, %1, %2, %0;" : "+l"(acc) : "l"(w), "l"(h));
}
__device__ __forceinline__ float sum2(ull a) {
    float lo, hi;
    asm("mov.b64 {%0, %1}, %2;" : "=f"(lo), "=f"(hi) : "l"(a));
    return lo + hi;
}

// ---------------- Phase 1: G = F @ W_x^T + (b_ih + b_hh) ----------------
// 128x128 tile, BK=32 (halves per-iteration fixed cost vs BK=16), 256 threads
// (8 warps: 2m x 4n of 64x32). 2-stage cp.async pipeline, 73.7KB dyn smem.
// Raw fp32 bits -> tf32 mma (HW truncation).
__global__ void __launch_bounds__(256) gemm_kernel(
    const float* __restrict__ x, const float* __restrict__ hi,
    const float* __restrict__ W_ih,
    const float* __restrict__ b_ih, const float* __restrict__ b_hh)
{
    extern __shared__ __align__(16) float smem[];
    float* sA = smem;                      // [2][128][AROW]
    float* sB = smem + 2 * 128 * AROW;     // [2][128][AROW]

    const int tid  = threadIdx.x;
    const int warp = tid >> 5, lane = tid & 31;
    const int grp  = lane >> 2, q = lane & 3;
    const int wm   = warp & 1;         // 0..1 -> 64-row m half
    const int wn   = warp >> 1;        // 0..3 -> 32-col n quarter
    const int tm0  = blockIdx.y * 128;
    const int rn0  = blockIdx.x * 128;

    const int ldRow = tid >> 2;        // 0..63 (+64 for second row half)
    const int ldCh  = tid & 3;         // chunk 0..3 (+4 for second chunk half)

    uint32_t aBase = (uint32_t)__cvta_generic_to_shared(sA);
    uint32_t bBase = (uint32_t)__cvta_generic_to_shared(sB);

    // one BK=32 stage of A+B via cp.async (4 chunks per array per thread)
    auto issue_stage = [&](int kt) {
        int stage = kt & 1;
        #pragma unroll
        for (int i = 0; i < 2; i++) {
            int row = ldRow + i * 64;
            #pragma unroll
            for (int c2 = 0; c2 < 2; c2++) {
                int chunk = ldCh + c2 * 4;
                int kg = kt * 32 + chunk * 4;
                const float* gA = (kg < 2048)
                    ? (x  + (size_t)(tm0 + row) * 2048 + kg)
                    : (hi + (size_t)(tm0 + row) * 2048 + kg - 2048);
                uint32_t dA = aBase + (((stage * 128 + row) * AROW) + chunk * 4) * 4;
                asm volatile("cp.async.cg.shared.global [%0], [%1], 16;" :: "r"(dA), "l"(gA));
                const float* gB = W_ih + (size_t)(rn0 + row) * IN5 + kg;
                uint32_t dB = bBase + (((stage * 128 + row) * AROW) + chunk * 4) * 4;
                asm volatile("cp.async.cg.shared.global [%0], [%1], 16;" :: "r"(dB), "l"(gB));
            }
        }
        asm volatile("cp.async.commit_group;");
    };

    float acc[4][4][4];
    #pragma unroll
    for (int a = 0; a < 4; a++)
        #pragma unroll
        for (int b = 0; b < 4; b++)
            #pragma unroll
            for (int c = 0; c < 4; c++) acc[a][b][c] = 0.f;

    issue_stage(0);

    for (int kt = 0; kt < 128; kt++) {
        if (kt < 127) {
            issue_stage(kt + 1);
            asm volatile("cp.async.wait_group 1;");   // group kt complete
        } else {
            asm volatile("cp.async.wait_group 0;");   // exact tail
        }
        __syncthreads();

        const float* A = sA + (kt & 1) * 128 * AROW;
        const float* B = sB + (kt & 1) * 128 * AROW;

        #pragma unroll
        for (int kk = 0; kk < 32; kk += 8) {
            uint32_t af[4][4], bf[4][2];
            #pragma unroll
            for (int mi = 0; mi < 4; mi++) {
                int rb = wm * 64 + mi * 16;
                af[mi][0] = __float_as_uint(A[(rb + grp    ) * AROW + kk + q    ]);
                af[mi][1] = __float_as_uint(A[(rb + grp + 8) * AROW + kk + q    ]);
                af[mi][2] = __float_as_uint(A[(rb + grp    ) * AROW + kk + q + 4]);
                af[mi][3] = __float_as_uint(A[(rb + grp + 8) * AROW + kk + q + 4]);
            }
            #pragma unroll
            for (int ni = 0; ni < 4; ni++) {
                int nb = wn * 32 + ni * 8;
                bf[ni][0] = __float_as_uint(B[(nb + grp) * AROW + kk + q    ]);
                bf[ni][1] = __float_as_uint(B[(nb + grp) * AROW + kk + q + 4]);
            }
            #pragma unroll
            for (int mi = 0; mi < 4; mi++)
                #pragma unroll
                for (int ni = 0; ni < 4; ni++)
                    mma_tf32(acc[mi][ni], af[mi], bf[ni]);
        }
        __syncthreads();   // readers of stage kt&1 done before its refill
    }

    #pragma unroll
    for (int mi = 0; mi < 4; mi++)
        #pragma unroll
        for (int ni = 0; ni < 4; ni++) {
            int r0 = tm0 + wm * 64 + mi * 16 + grp;
            int c0 = rn0 + wn * 32 + ni * 8 + 2 * q;
            float bia0 = b_ih[c0]     + b_hh[c0];
            float bia1 = b_ih[c0 + 1] + b_hh[c0 + 1];
            g_G[(size_t)r0 * G4 + c0]           = acc[mi][ni][0] + bia0;
            g_G[(size_t)r0 * G4 + c0 + 1]       = acc[mi][ni][1] + bia1;
            g_G[(size_t)(r0 + 8) * G4 + c0]     = acc[mi][ni][2] + bia0;
            g_G[(size_t)(r0 + 8) * G4 + c0 + 1] = acc[mi][ni][3] + bia1;
        }
}

// ---------------- Phase 2: persistent recurrence (FROZEN from R9/R10/R12) ----------------
// 128 CTAs x 544 threads: warps 0-15 = dot warps (register-resident W_r),
// warp 16 = epilogue warp. Sentinel handoff, rotating 2-in-flight poll,
// bar.arrive/bar.sync split.
__global__ void __launch_bounds__(544, 1) recur_kernel(
    const float* __restrict__ W_ih, const float* __restrict__ W_hh)
{
    __shared__ float sh_h[HD];            // warp-private 64-float slices
    __shared__ float sh_part[2][16][32];  // parity double buffer

    const int tid  = threadIdx.x;
    const int w    = tid >> 5, l = tid & 31;
    const int gate = l >> 3, jl = l & 7;
    const int j    = blockIdx.x * 8 + jl;
    const int rg   = gate * HD + j;
    const bool dot_warp = (w < 16);
    const int kb   = (w & 15) * 64;

    // dot warps: fuse recurrent weights, packed f32x2 (fp32-exact)
    ull pw[32];
    if (dot_warp) {
        #pragma unroll
        for (int i = 0; i < 16; i++) {
            float4 a = *(const float4*)(W_ih + (size_t)rg * IN5 + G4 + kb + 4 * i);
            float4 b = *(const float4*)(W_hh + (size_t)rg * HD + kb + 4 * i);
            pw[2*i]   = packf2(a.x + b.x, a.y + b.y);
            pw[2*i+1] = packf2(a.z + b.z, a.w + b.w);
        }
    }

    float c = 0.f;          // cell state (epilogue warp, lanes 0-7)

    for (int t = 0; t < LSEQ; t++) {
        if (dot_warp) {
            float partial = 0.f;
            if (t > 0) {
                // rotating 2-in-flight poll: lane owns 8B of the 64-float slice
                const float* p = g_outs + (size_t)(t - 1) * HD + kb + 2 * l;
                float2 a, b, hv;
                bool got = false;
                asm volatile("ld.global.cg.v2.f32 {%0,%1}, [%2];"
                             : "=f"(a.x), "=f"(a.y) : "l"(p));
                asm volatile("ld.global.cg.v2.f32 {%0,%1}, [%2];"
                             : "=f"(b.x), "=f"(b.y) : "l"(p));
                for (;;) {
                    if (!got && __float_as_uint(a.y) != SENT
                             && __float_as_uint(a.x) != SENT) { hv = a; got = true; }
                    if (__all_sync(0xffffffffu, got)) break;
                    asm volatile("ld.global.cg.v2.f32 {%0,%1}, [%2];"
                                 : "=f"(a.x), "=f"(a.y) : "l"(p));
                    if (!got && __float_as_uint(b.y) != SENT
                             && __float_as_uint(b.x) != SENT) { hv = b; got = true; }
                    if (__all_sync(0xffffffffu, got)) break;
                    asm volatile("ld.global.cg.v2.f32 {%0,%1}, [%2];"
                                 : "=f"(b.x), "=f"(b.y) : "l"(p));
                }
                ((float2*)(sh_h + kb))[l] = hv;
                __syncwarp();

                // dot: 32 FFMA2 against packed register weights
                ull a0 = packf2(0.f, 0.f), a1 = packf2(0.f, 0.f);
                const ulonglong2* h8 = (const ulonglong2*)(sh_h + kb);
                #pragma unroll
                for (int i = 0; i < 16; i++) {
                    ulonglong2 hvv = h8[i];
                    fma2(a0, pw[2*i],     hvv.x);
                    fma2(a1, pw[2*i + 1], hvv.y);
                }
                partial = sum2(a0) + sum2(a1);
            }
            sh_part[t & 1][w][l] = partial;
            // arrive-only: roll straight into next step's poll
            asm volatile("bar.arrive 1, 544;");
        } else {
            // epilogue warp: prefetch gate pre-activations while dots run
            float gpre = __ldcg(&g_G[(size_t)t * G4 + rg]);
            asm volatile("bar.sync 1, 544;");   // waits for all 512 dot threads

            // reduce 16 partials (tree)
            float p0 = sh_part[t & 1][0][l],  p1 = sh_part[t & 1][1][l];
            float p2 = sh_part[t & 1][2][l],  p3 = sh_part[t & 1][3][l];
            float p4 = sh_part[t & 1][4][l],  p5 = sh_part[t & 1][5][l];
            float p6 = sh_part[t & 1][6][l],  p7 = sh_part[t & 1][7][l];
            float p8 = sh_part[t & 1][8][l],  p9 = sh_part[t & 1][9][l];
            float pA = sh_part[t & 1][10][l], pB = sh_part[t & 1][11][l];
            float pC = sh_part[t & 1][12][l], pD = sh_part[t & 1][13][l];
            float pE = sh_part[t & 1][14][l], pF = sh_part[t & 1][15][l];
            float s = gpre + (((p0+p1)+(p2+p3)) + ((p4+p5)+(p6+p7)))
                           + (((p8+p9)+(pA+pB)) + ((pC+pD)+(pE+pF)));

            // parallel per-gate nonlinearity BEFORE gather (1 expf, all lanes)
            float arg = (gate == 2) ? (2.f * s) : s;
            float e   = __expf(-arg);
            float sig = __fdividef(1.f, 1.f + e);
            float v   = (gate == 2) ? (2.f * sig - 1.f) : sig;   // tanh for 'g'

            float ig = __shfl_sync(0xffffffffu, v, jl);
            float fg = __shfl_sync(0xffffffffu, v, jl + 8);
            float tg = __shfl_sync(0xffffffffu, v, jl + 16);
            float og = __shfl_sync(0xffffffffu, v, jl + 24);
            if (l < 8) {
                c = fg * c + ig * tg;
                float tc = 2.f * __fdividef(1.f, 1.f + __expf(-2.f * c)) - 1.f;
                float hn = og * tc;
                // single coalesced sector store = data + readiness in one shot
                __stcg(&g_outs[(size_t)t * HD + j], hn);
            }
        }
    }
}

// ---------------- Phase 3: out = outs @ W_fc^T + b_fc (tiled) ----------------
#define FC_TT 4
__global__ void __launch_bounds__(128) fc_kernel(
    const float* __restrict__ W_fc, const float* __restrict__ b_fc,
    float* __restrict__ out)
{
    __shared__ float sw[LAB][65];
    __shared__ float so[FC_TT][64];

    const int tid = threadIdx.x;
    const int t0  = blockIdx.x * FC_TT;

    float acc[FC_TT];
    #pragma unroll
    for (int tt = 0; tt < FC_TT; tt++) acc[tt] = 0.f;

    for (int kc = 0; kc < HD; kc += 64) {
        for (int idx = tid; idx < LAB * 64; idx += 128) {
            int r = idx >> 6, cc = idx & 63;
            sw[r][cc] = W_fc[(size_t)r * HD + kc + cc];
        }
        for (int idx = tid; idx < FC_TT * 64; idx += 128) {
            int tt = idx >> 6, cc = idx & 63;
            so[tt][cc] = g_outs[(size_t)(t0 + tt) * HD + kc + cc];
        }
        __syncthreads();

        if (tid < LAB) {
            #pragma unroll
            for (int k = 0; k < 64; k += 4) {
                float w0 = sw[tid][k], w1 = sw[tid][k+1];
                float w2 = sw[tid][k+2], w3 = sw[tid][k+3];
                #pragma unroll
                for (int tt = 0; tt < FC_TT; tt++) {
                    float4 ov = *(const float4*)&so[tt][k];
                    acc[tt] += w0*ov.x + w1*ov.y + w2*ov.z + w3*ov.w;
                }
            }
        }
        __syncthreads();
    }

    if (tid < LAB) {
        float bb = b_fc[tid];
        #pragma unroll
        for (int tt = 0; tt < FC_TT; tt++)
            out[(size_t)(t0 + tt) * LAB + tid] = acc[tt] + bb;
    }
}

// ---------------- launch ----------------
extern "C" void kernel_launch(void* const* d_in, const int* in_sizes, int n_in,
                              void* d_out, int out_size)
{
    const float* x    = (const float*)d_in[0];
    const float* hi   = (const float*)d_in[1];
    const float* W_ih = (const float*)d_in[2];
    const float* W_hh = (const float*)d_in[3];
    const float* b_ih = (const float*)d_in[4];
    const float* b_hh = (const float*)d_in[5];
    const float* W_fc = (const float*)d_in[6];
    const float* b_fc = (const float*)d_in[7];
    float* out = (float*)d_out;

    static bool attr_done = false;
    if (!attr_done) {
        cudaFuncSetAttribute(gemm_kernel,
                             cudaFuncAttributeMaxDynamicSharedMemorySize, GEMM_SMEM);
        attr_done = true;
    }

    pad_kernel<<<1, 32>>>();                            // idx 0
    pad_kernel<<<1, 32>>>();                            // idx 1
    reset_kernel<<<512, 512>>>();                       // idx 2: poison g_outs
    gemm_kernel<<<dim3(G4 / 128, LSEQ / 128), 256, GEMM_SMEM>>>(x, hi, W_ih, b_ih, b_hh); // idx 3 -> ncu
    recur_kernel<<<NCTA, 544>>>(W_ih, W_hh);            // idx 4
    fc_kernel<<<LSEQ / FC_TT, 128>>>(W_fc, b_fc, out);  // idx 5
}

// round 14
// speedup vs baseline: 1.0222x; 1.0045x over previous
#include <cuda_runtime.h>
#include <cstdint>

#define HD   1024
#define LSEQ 512
#define LAB  122
#define G4   (4*HD)     // 4096
#define IN5  (5*HD)     // 5120
#define NCTA 128
#define SENT 0x7FC00000u   // qNaN sentinel
#define AROW 36            // 32 k-floats + 4 pad (conflict-free: 36 mod 32 = 4)
#define GEMM_SMEM (2 * 128 * AROW * 4 * 2)   // 73728 B (2 stages, A + B)

typedef unsigned long long ull;

// ---------------- scratch (static __device__, no allocs) ----------------
__device__ float g_G[(size_t)LSEQ * G4];     // precomputed input gates + bias (8 MB)
__device__ float g_outs[(size_t)LSEQ * HD];  // h_t for all t; doubles as sync medium (2 MB)

// ---------------- ncu steering pads (no-op); gemm must be launch index 3 ----
__global__ void pad_kernel() {}

// ---------------- reset: poison g_outs with sentinel ----------------
__global__ void reset_kernel() {
    size_t i = (size_t)blockIdx.x * blockDim.x + threadIdx.x;
    uint32_t* p = (uint32_t*)g_outs;
    p[2 * i]     = SENT;
    p[2 * i + 1] = SENT;
}

// ---------------- mma helper ----------------
__device__ __forceinline__ void mma_tf32(float* d, const uint32_t* a, const uint32_t* b) {
    asm volatile(
        "mma.sync.aligned.m16n8k8.row.col.f32.tf32.tf32.f32 "
        "{%0,%1,%2,%3}, {%4,%5,%6,%7}, {%8,%9}, {%0,%1,%2,%3};\n"
        : "+f"(d[0]), "+f"(d[1]), "+f"(d[2]), "+f"(d[3])
        : "r"(a[0]), "r"(a[1]), "r"(a[2]), "r"(a[3]), "r"(b[0]), "r"(b[1]));
}

// ---------------- packed f32x2 helpers ----------------
__device__ __forceinline__ ull packf2(float lo, float hi) {
    ull p;
    asm("mov.b64 %0, {%1, %2};" : "=l"(p) : "f"(lo), "f"(hi));
    return p;
}
__device__ __forceinline__ void fma2(ull& acc, ull w, ull h) {
    asm("fma.rn.f32x2 %0, %1, %2, %0;" : "+l"(acc) : "l"(w), "l"(h));
}
__device__ __forceinline__ float sum2(ull a) {
    float lo, hi;
    asm("mov.b64 {%0, %1}, %2;" : "=f"(lo), "=f"(hi) : "l"(a));
    return lo + hi;
}

// ---------------- Phase 1: G = F @ W_x^T + (b_ih + b_hh) ----------------
// 128x128 tile, BK=32, 512 threads = 16 warps (2m x 8n of 64x16).
// 4 warps/SMSP hide scalar-LDS latency that capped the 8-warp version at
// tensor=34% (R13 profile). 2-stage cp.async pipeline, 73.7KB dyn smem.
__global__ void __launch_bounds__(512) gemm_kernel(
    const float* __restrict__ x, const float* __restrict__ hi,
    const float* __restrict__ W_ih,
    const float* __restrict__ b_ih, const float* __restrict__ b_hh)
{
    extern __shared__ __align__(16) float smem[];
    float* sA = smem;                      // [2][128][AROW]
    float* sB = smem + 2 * 128 * AROW;     // [2][128][AROW]

    const int tid  = threadIdx.x;
    const int warp = tid >> 5, lane = tid & 31;
    const int grp  = lane >> 2, q = lane & 3;
    const int wm   = warp & 1;         // 0..1 -> 64-row m half
    const int wn   = warp >> 1;        // 0..7 -> 16-col n slice
    const int tm0  = blockIdx.y * 128;
    const int rn0  = blockIdx.x * 128;

    const int ldRow = tid >> 3;        // 0..63 (+64 for second row half)
    const int ldCh  = tid & 7;         // chunk 0..7 of the 32-float k slab

    uint32_t aBase = (uint32_t)__cvta_generic_to_shared(sA);
    uint32_t bBase = (uint32_t)__cvta_generic_to_shared(sB);

    // one BK=32 stage of A+B via cp.async (2 rows per array per thread)
    auto issue_stage = [&](int kt) {
        int stage = kt & 1;
        int kg = kt * 32 + ldCh * 4;
        #pragma unroll
        for (int i = 0; i < 2; i++) {
            int row = ldRow + i * 64;
            const float* gA = (kg < 2048)
                ? (x  + (size_t)(tm0 + row) * 2048 + kg)
                : (hi + (size_t)(tm0 + row) * 2048 + kg - 2048);
            uint32_t dA = aBase + (((stage * 128 + row) * AROW) + ldCh * 4) * 4;
            asm volatile("cp.async.cg.shared.global [%0], [%1], 16;" :: "r"(dA), "l"(gA));
            const float* gB = W_ih + (size_t)(rn0 + row) * IN5 + kg;
            uint32_t dB = bBase + (((stage * 128 + row) * AROW) + ldCh * 4) * 4;
            asm volatile("cp.async.cg.shared.global [%0], [%1], 16;" :: "r"(dB), "l"(gB));
        }
        asm volatile("cp.async.commit_group;");
    };

    float acc[4][2][4];
    #pragma unroll
    for (int a = 0; a < 4; a++)
        #pragma unroll
        for (int b = 0; b < 2; b++)
            #pragma unroll
            for (int c = 0; c < 4; c++) acc[a][b][c] = 0.f;

    issue_stage(0);

    for (int kt = 0; kt < 128; kt++) {
        if (kt < 127) {
            issue_stage(kt + 1);
            asm volatile("cp.async.wait_group 1;");   // group kt complete
        } else {
            asm volatile("cp.async.wait_group 0;");   // exact tail
        }
        __syncthreads();

        const float* A = sA + (kt & 1) * 128 * AROW;
        const float* B = sB + (kt & 1) * 128 * AROW;

        #pragma unroll
        for (int kk = 0; kk < 32; kk += 8) {
            uint32_t af[4][4], bf[2][2];
            #pragma unroll
            for (int mi = 0; mi < 4; mi++) {
                int rb = wm * 64 + mi * 16;
                af[mi][0] = __float_as_uint(A[(rb + grp    ) * AROW + kk + q    ]);
                af[mi][1] = __float_as_uint(A[(rb + grp + 8) * AROW + kk + q    ]);
                af[mi][2] = __float_as_uint(A[(rb + grp    ) * AROW + kk + q + 4]);
                af[mi][3] = __float_as_uint(A[(rb + grp + 8) * AROW + kk + q + 4]);
            }
            #pragma unroll
            for (int ni = 0; ni < 2; ni++) {
                int nb = wn * 16 + ni * 8;
                bf[ni][0] = __float_as_uint(B[(nb + grp) * AROW + kk + q    ]);
                bf[ni][1] = __float_as_uint(B[(nb + grp) * AROW + kk + q + 4]);
            }
            #pragma unroll
            for (int mi = 0; mi < 4; mi++)
                #pragma unroll
                for (int ni = 0; ni < 2; ni++)
                    mma_tf32(acc[mi][ni], af[mi], bf[ni]);
        }
        __syncthreads();   // readers of stage kt&1 done before its refill
    }

    #pragma unroll
    for (int mi = 0; mi < 4; mi++)
        #pragma unroll
        for (int ni = 0; ni < 2; ni++) {
            int r0 = tm0 + wm * 64 + mi * 16 + grp;
            int c0 = rn0 + wn * 16 + ni * 8 + 2 * q;
            float bia0 = b_ih[c0]     + b_hh[c0];
            float bia1 = b_ih[c0 + 1] + b_hh[c0 + 1];
            g_G[(size_t)r0 * G4 + c0]           = acc[mi][ni][0] + bia0;
            g_G[(size_t)r0 * G4 + c0 + 1]       = acc[mi][ni][1] + bia1;
            g_G[(size_t)(r0 + 8) * G4 + c0]     = acc[mi][ni][2] + bia0;
            g_G[(size_t)(r0 + 8) * G4 + c0 + 1] = acc[mi][ni][3] + bia1;
        }
}

// ---------------- Phase 2: persistent recurrence (FROZEN from R9/R10/R12) ----------------
// 128 CTAs x 544 threads: warps 0-15 = dot warps (register-resident W_r),
// warp 16 = epilogue warp. Sentinel handoff, rotating 2-in-flight poll,
// bar.arrive/bar.sync split.
__global__ void __launch_bounds__(544, 1) recur_kernel(
    const float* __restrict__ W_ih, const float* __restrict__ W_hh)
{
    __shared__ float sh_h[HD];            // warp-private 64-float slices
    __shared__ float sh_part[2][16][32];  // parity double buffer

    const int tid  = threadIdx.x;
    const int w    = tid >> 5, l = tid & 31;
    const int gate = l >> 3, jl = l & 7;
    const int j    = blockIdx.x * 8 + jl;
    const int rg   = gate * HD + j;
    const bool dot_warp = (w < 16);
    const int kb   = (w & 15) * 64;

    // dot warps: fuse recurrent weights, packed f32x2 (fp32-exact)
    ull pw[32];
    if (dot_warp) {
        #pragma unroll
        for (int i = 0; i < 16; i++) {
            float4 a = *(const float4*)(W_ih + (size_t)rg * IN5 + G4 + kb + 4 * i);
            float4 b = *(const float4*)(W_hh + (size_t)rg * HD + kb + 4 * i);
            pw[2*i]   = packf2(a.x + b.x, a.y + b.y);
            pw[2*i+1] = packf2(a.z + b.z, a.w + b.w);
        }
    }

    float c = 0.f;          // cell state (epilogue warp, lanes 0-7)

    for (int t = 0; t < LSEQ; t++) {
        if (dot_warp) {
            float partial = 0.f;
            if (t > 0) {
                // rotating 2-in-flight poll: lane owns 8B of the 64-float slice
                const float* p = g_outs + (size_t)(t - 1) * HD + kb + 2 * l;
                float2 a, b, hv;
                bool got = false;
                asm volatile("ld.global.cg.v2.f32 {%0,%1}, [%2];"
                             : "=f"(a.x), "=f"(a.y) : "l"(p));
                asm volatile("ld.global.cg.v2.f32 {%0,%1}, [%2];"
                             : "=f"(b.x), "=f"(b.y) : "l"(p));
                for (;;) {
                    if (!got && __float_as_uint(a.y) != SENT
                             && __float_as_uint(a.x) != SENT) { hv = a; got = true; }
                    if (__all_sync(0xffffffffu, got)) break;
                    asm volatile("ld.global.cg.v2.f32 {%0,%1}, [%2];"
                                 : "=f"(a.x), "=f"(a.y) : "l"(p));
                    if (!got && __float_as_uint(b.y) != SENT
                             && __float_as_uint(b.x) != SENT) { hv = b; got = true; }
                    if (__all_sync(0xffffffffu, got)) break;
                    asm volatile("ld.global.cg.v2.f32 {%0,%1}, [%2];"
                                 : "=f"(b.x), "=f"(b.y) : "l"(p));
                }
                ((float2*)(sh_h + kb))[l] = hv;
                __syncwarp();

                // dot: 32 FFMA2 against packed register weights
                ull a0 = packf2(0.f, 0.f), a1 = packf2(0.f, 0.f);
                const ulonglong2* h8 = (const ulonglong2*)(sh_h + kb);
                #pragma unroll
                for (int i = 0; i < 16; i++) {
                    ulonglong2 hvv = h8[i];
                    fma2(a0, pw[2*i],     hvv.x);
                    fma2(a1, pw[2*i + 1], hvv.y);
                }
                partial = sum2(a0) + sum2(a1);
            }
            sh_part[t & 1][w][l] = partial;
            // arrive-only: roll straight into next step's poll
            asm volatile("bar.arrive 1, 544;");
        } else {
            // epilogue warp: prefetch gate pre-activations while dots run
            float gpre = __ldcg(&g_G[(size_t)t * G4 + rg]);
            asm volatile("bar.sync 1, 544;");   // waits for all 512 dot threads

            // reduce 16 partials (tree)
            float p0 = sh_part[t & 1][0][l],  p1 = sh_part[t & 1][1][l];
            float p2 = sh_part[t & 1][2][l],  p3 = sh_part[t & 1][3][l];
            float p4 = sh_part[t & 1][4][l],  p5 = sh_part[t & 1][5][l];
            float p6 = sh_part[t & 1][6][l],  p7 = sh_part[t & 1][7][l];
            float p8 = sh_part[t & 1][8][l],  p9 = sh_part[t & 1][9][l];
            float pA = sh_part[t & 1][10][l], pB = sh_part[t & 1][11][l];
            float pC = sh_part[t & 1][12][l], pD = sh_part[t & 1][13][l];
            float pE = sh_part[t & 1][14][l], pF = sh_part[t & 1][15][l];
            float s = gpre + (((p0+p1)+(p2+p3)) + ((p4+p5)+(p6+p7)))
                           + (((p8+p9)+(pA+pB)) + ((pC+pD)+(pE+pF)));

            // parallel per-gate nonlinearity BEFORE gather (1 expf, all lanes)
            float arg = (gate == 2) ? (2.f * s) : s;
            float e   = __expf(-arg);
            float sig = __fdividef(1.f, 1.f + e);
            float v   = (gate == 2) ? (2.f * sig - 1.f) : sig;   // tanh for 'g'

            float ig = __shfl_sync(0xffffffffu, v, jl);
            float fg = __shfl_sync(0xffffffffu, v, jl + 8);
            float tg = __shfl_sync(0xffffffffu, v, jl + 16);
            float og = __shfl_sync(0xffffffffu, v, jl + 24);
            if (l < 8) {
                c = fg * c + ig * tg;
                float tc = 2.f * __fdividef(1.f, 1.f + __expf(-2.f * c)) - 1.f;
                float hn = og * tc;
                // single coalesced sector store = data + readiness in one shot
                __stcg(&g_outs[(size_t)t * HD + j], hn);
            }
        }
    }
}

// ---------------- Phase 3: out = outs @ W_fc^T + b_fc (tiled) ----------------
#define FC_TT 4
__global__ void __launch_bounds__(128) fc_kernel(
    const float* __restrict__ W_fc, const float* __restrict__ b_fc,
    float* __restrict__ out)
{
    __shared__ float sw[LAB][65];
    __shared__ float so[FC_TT][64];

    const int tid = threadIdx.x;
    const int t0  = blockIdx.x * FC_TT;

    float acc[FC_TT];
    #pragma unroll
    for (int tt = 0; tt < FC_TT; tt++) acc[tt] = 0.f;

    for (int kc = 0; kc < HD; kc += 64) {
        for (int idx = tid; idx < LAB * 64; idx += 128) {
            int r = idx >> 6, cc = idx & 63;
            sw[r][cc] = W_fc[(size_t)r * HD + kc + cc];
        }
        for (int idx = tid; idx < FC_TT * 64; idx += 128) {
            int tt = idx >> 6, cc = idx & 63;
            so[tt][cc] = g_outs[(size_t)(t0 + tt) * HD + kc + cc];
        }
        __syncthreads();

        if (tid < LAB) {
            #pragma unroll
            for (int k = 0; k < 64; k += 4) {
                float w0 = sw[tid][k], w1 = sw[tid][k+1];
                float w2 = sw[tid][k+2], w3 = sw[tid][k+3];
                #pragma unroll
                for (int tt = 0; tt < FC_TT; tt++) {
                    float4 ov = *(const float4*)&so[tt][k];
                    acc[tt] += w0*ov.x + w1*ov.y + w2*ov.z + w3*ov.w;
                }
            }
        }
        __syncthreads();
    }

    if (tid < LAB) {
        float bb = b_fc[tid];
        #pragma unroll
        for (int tt = 0; tt < FC_TT; tt++)
            out[(size_t)(t0 + tt) * LAB + tid] = acc[tt] + bb;
    }
}

// ---------------- launch ----------------
extern "C" void kernel_launch(void* const* d_in, const int* in_sizes, int n_in,
                              void* d_out, int out_size)
{
    const float* x    = (const float*)d_in[0];
    const float* hi   = (const float*)d_in[1];
    const float* W_ih = (const float*)d_in[2];
    const float* W_hh = (const float*)d_in[3];
    const float* b_ih = (const float*)d_in[4];
    const float* b_hh = (const float*)d_in[5];
    const float* W_fc = (const float*)d_in[6];
    const float* b_fc = (const float*)d_in[7];
    float* out = (float*)d_out;

    static bool attr_done = false;
    if (!attr_done) {
        cudaFuncSetAttribute(gemm_kernel,
                             cudaFuncAttributeMaxDynamicSharedMemorySize, GEMM_SMEM);
        attr_done = true;
    }

    pad_kernel<<<1, 32>>>();                            // idx 0
    pad_kernel<<<1, 32>>>();                            // idx 1
    reset_kernel<<<512, 512>>>();                       // idx 2: poison g_outs
    gemm_kernel<<<dim3(G4 / 128, LSEQ / 128), 512, GEMM_SMEM>>>(x, hi, W_ih, b_ih, b_hh); // idx 3 -> ncu
    recur_kernel<<<NCTA, 544>>>(W_ih, W_hh);            // idx 4
    fc_kernel<<<LSEQ / FC_TT, 128>>>(W_fc, b_fc, out);  // idx 5
}